// round 5
// baseline (speedup 1.0000x reference)
#include <cuda_runtime.h>

// Problem constants (shapes fixed by setup_inputs)
#define Bc   8
#define Nc   4096
#define Cc   64
#define COc  128
#define KNN  8
#define CAP  2048            /* candidate capacity per row (mean ~600, >25 sigma margin) */

#define ROWS_TOTAL   (Bc*Nc)           /* 32768 */
#define CONV_ROWS    16
#define CONV_BLOCKS  (ROWS_TOTAL/CONV_ROWS)  /* 2048 */

// ---------------- scratch (device globals: no runtime allocation) ----------
__device__ float g_xx[Bc*Nc];                       // per-point squared norms
__device__ int   g_cnt[Bc*Nc];                      // per-row candidate counts
__device__ uint2 g_cand[(size_t)Nc*CAP];            // 64MB candidate buffer (reused per batch)
__device__ float g_feat[(size_t)ROWS_TOTAL*Cc];     // 8MB  gathered-max features
__device__ float g_psum[CONV_BLOCKS*COc];           // BN partial sums (deterministic)
__device__ float g_psumsq[CONV_BLOCKS*COc];
__device__ float g_mean[COc];
__device__ float g_rstd[COc];

// ---------------- squared norms + counter zeroing ---------------------------
__global__ __launch_bounds__(256) void k_xx(const float* __restrict__ x)
{
    int gw   = (blockIdx.x*256 + threadIdx.x) >> 5;   // warp per row
    int lane = threadIdx.x & 31;
    if (gw >= ROWS_TOTAL) return;
    const float* xr = x + (size_t)gw*Cc;
    float a = xr[lane], b = xr[lane+32];
    float s = a*a + b*b;
    #pragma unroll
    for (int o=16;o;o>>=1) s += __shfl_xor_sync(0xffffffffu, s, o);
    if (lane == 0){ g_xx[gw] = s; g_cnt[gw] = 0; }
}

// ---------------- distance GEMM + fused per-tile top-k candidate filter -----
// D[n][m] = 2*<x_n,x_m> - xx_n - xx_m ; survivors (>= provably-safe per-tile
// threshold) are appended to per-row candidate lists. No 64MB dist matrix.
__global__ __launch_bounds__(256) void k_dist(const float* __restrict__ x, int b)
{
    __shared__ float As[32][128];   // k-major
    __shared__ float Bs[32][128];
    const float* xb = x + (size_t)b*Nc*Cc;
    const int n0  = blockIdx.y*128;
    const int m0  = blockIdx.x*128;
    const int tid = threadIdx.x;
    const int tx  = tid & 15;
    const int ty  = tid >> 4;
    const int lane = tid & 31;
    const int lgrp = lane & 15;     // position within the 16-lane row group
    const int lrow = tid & 127;
    const int lk0  = (tid >> 7) * 4;

    float acc[8][8];
    #pragma unroll
    for (int i=0;i<8;i++)
        #pragma unroll
        for (int j=0;j<8;j++) acc[i][j] = 0.f;

    #pragma unroll
    for (int kk=0; kk<2; kk++){
        #pragma unroll
        for (int i=0;i<4;i++){
            int k4 = lk0 + i*8;
            float4 a = *reinterpret_cast<const float4*>(&xb[(size_t)(n0+lrow)*Cc + kk*32 + k4]);
            As[k4+0][lrow]=a.x; As[k4+1][lrow]=a.y; As[k4+2][lrow]=a.z; As[k4+3][lrow]=a.w;
            float4 bb = *reinterpret_cast<const float4*>(&xb[(size_t)(m0+lrow)*Cc + kk*32 + k4]);
            Bs[k4+0][lrow]=bb.x; Bs[k4+1][lrow]=bb.y; Bs[k4+2][lrow]=bb.z; Bs[k4+3][lrow]=bb.w;
        }
        __syncthreads();
        #pragma unroll
        for (int k=0;k<32;k++){
            float4 a0 = *reinterpret_cast<const float4*>(&As[k][ty*4]);
            float4 a1 = *reinterpret_cast<const float4*>(&As[k][64+ty*4]);
            float4 b0 = *reinterpret_cast<const float4*>(&Bs[k][tx*4]);
            float4 b1 = *reinterpret_cast<const float4*>(&Bs[k][64+tx*4]);
            float av[8]={a0.x,a0.y,a0.z,a0.w,a1.x,a1.y,a1.z,a1.w};
            float bv[8]={b0.x,b0.y,b0.z,b0.w,b1.x,b1.y,b1.z,b1.w};
            #pragma unroll
            for (int i=0;i<8;i++)
                #pragma unroll
                for (int j=0;j<8;j++)
                    acc[i][j] = fmaf(av[i], bv[j], acc[i][j]);
        }
        __syncthreads();
    }

    float mxx[8];
    #pragma unroll
    for (int cq=0;cq<2;cq++)
        #pragma unroll
        for (int c=0;c<4;c++)
            mxx[cq*4+c] = g_xx[b*Nc + m0 + cq*64 + tx*4 + c];

    // Epilogue: per row, build candidates. The 16 threads with the same ty
    // (lanes 0-15 or 16-31 of a warp) share the same 8 rows.
    #pragma unroll
    for (int rq=0;rq<2;rq++){
        #pragma unroll
        for (int r=0;r<4;r++){
            int row = n0 + rq*64 + ty*4 + r;
            float xn = g_xx[b*Nc + row];
            int ai = rq*4 + r;
            float d[8];
            #pragma unroll
            for (int j=0;j<8;j++) d[j] = 2.f*acc[ai][j] - xn - mxx[j];

            // threshold: min of 8 distinct 16-element block maxes (t <= true 8th best of this tile row)
            float m = d[0];
            #pragma unroll
            for (int j=1;j<8;j++) m = fmaxf(m, d[j]);
            float t = fmaxf(m, __shfl_xor_sync(0xffffffffu, m, 8));
            t = fminf(t, __shfl_xor_sync(0xffffffffu, t, 4));
            t = fminf(t, __shfl_xor_sync(0xffffffffu, t, 2));
            t = fminf(t, __shfl_xor_sync(0xffffffffu, t, 1));

            // flag survivors, prefix-scan counts over the 16-lane group
            int cnt = 0;
            bool f[8];
            #pragma unroll
            for (int j=0;j<8;j++){ f[j] = (d[j] >= t); cnt += f[j] ? 1 : 0; }
            int inc = cnt;
            #pragma unroll
            for (int o=1;o<16;o<<=1){
                int v = __shfl_up_sync(0xffffffffu, inc, o, 16);
                if (lgrp >= o) inc += v;
            }
            int total = __shfl_sync(0xffffffffu, inc, 15, 16);
            int base = 0;
            if (lgrp == 15) base = atomicAdd(&g_cnt[b*Nc + row], total);
            base = __shfl_sync(0xffffffffu, base, 15, 16);
            int off = base + inc - cnt;
            uint2* bufrow = &g_cand[(size_t)(row - 0)*0];  // placeholder (avoid unused warn)
            (void)bufrow;
            uint2* brow = &g_cand[(size_t)(row & (Nc-1))*CAP];
            #pragma unroll
            for (int j=0;j<8;j++){
                if (f[j]){
                    if (off < CAP){
                        int col = m0 + (j>>2)*64 + tx*4 + (j&3);
                        brow[off] = make_uint2(__float_as_uint(d[j]), (unsigned)col);
                    }
                    off++;
                }
            }
        }
    }
}

// ---------------- exact top-k(8) over candidates + gather + channel max -----
__device__ __forceinline__ bool knn_better(float v1,int i1,float v2,int i2){
    return (v1 > v2) || (v1 == v2 && i1 < i2);   // matches lax.top_k tie-break
}

__device__ __forceinline__ void knn_insert(float (&v)[8], int (&id)[8], float cv, int ci){
    if (!knn_better(cv,ci,v[7],id[7])) return;
    #pragma unroll
    for (int j=0;j<8;j++){
        if (knn_better(cv,ci,v[j],id[j])){
            float tv=v[j]; int ti=id[j];
            v[j]=cv; id[j]=ci;
            cv=tv; ci=ti;
        }
    }
}

__global__ __launch_bounds__(256) void k_select(const float* __restrict__ x, int b)
{
    int gw   = (blockIdx.x*256 + threadIdx.x) >> 5;   // warp per n-row
    int lane = threadIdx.x & 31;
    if (gw >= Nc) return;
    const int n = gw;
    int cnt = g_cnt[b*Nc + n];
    if (cnt > CAP) cnt = CAP;
    const uint2* brow = &g_cand[(size_t)n*CAP];

    float v[8]; int id[8];
    #pragma unroll
    for (int j=0;j<8;j++){ v[j] = __int_as_float(0xff800000u); id[j] = 0x7fffffff; }

    for (int ci = lane; ci < cnt; ci += 32){
        uint2 e = brow[ci];
        knn_insert(v, id, __uint_as_float(e.x), (int)e.y);
    }

    int knn_idx[8];
    #pragma unroll
    for (int r=0;r<KNN;r++){
        float bv = v[0]; int bi = id[0];
        #pragma unroll
        for (int o=16;o;o>>=1){
            float ov = __shfl_xor_sync(0xffffffffu, bv, o);
            int   oi = __shfl_xor_sync(0xffffffffu, bi, o);
            if (knn_better(ov,oi,bv,bi)){ bv=ov; bi=oi; }
        }
        knn_idx[r] = bi;                 // all lanes agree
        if (id[0] == bi){                // owning lane pops its head
            #pragma unroll
            for (int j=0;j<7;j++){ v[j]=v[j+1]; id[j]=id[j+1]; }
            v[7] = __int_as_float(0xff800000u); id[7] = 0x7fffffff;
        }
    }

    // gather neighbor features and take channel-wise max (exact, order-free)
    const float* xb = x + (size_t)b*Nc*Cc;
    #pragma unroll
    for (int cc=0; cc<2; cc++){
        int c = lane + cc*32;
        float m = xb[(size_t)knn_idx[0]*Cc + c];
        #pragma unroll
        for (int r=1;r<KNN;r++)
            m = fmaxf(m, xb[(size_t)knn_idx[r]*Cc + c]);
        g_feat[((size_t)b*Nc + n)*Cc + c] = m;
    }
}

// ---------------- 1x1 conv GEMM + deterministic BN partials -----------------
__global__ __launch_bounds__(128) void k_conv(const float* __restrict__ W,
                                              float* __restrict__ y)
{
    __shared__ float Ws[COc][Cc+1];   // +1 pad: conflict-free per-thread rows
    __shared__ float Fs[CONV_ROWS][Cc];
    const int t    = threadIdx.x;     // 128 threads == one output channel each
    const int blk  = blockIdx.x;
    const int row0 = blk*CONV_ROWS;

    for (int i=t; i<COc*Cc; i+=128) Ws[i>>6][i&63] = W[i];
    for (int i=t; i<CONV_ROWS*Cc; i+=128) Fs[i>>6][i&63] = g_feat[(size_t)row0*Cc + i];
    __syncthreads();

    const int o = t;
    float acc[CONV_ROWS];
    #pragma unroll
    for (int r=0;r<CONV_ROWS;r++) acc[r]=0.f;

    #pragma unroll 8
    for (int k=0;k<Cc;k++){
        float w = Ws[o][k];
        #pragma unroll
        for (int r=0;r<CONV_ROWS;r++)
            acc[r] = fmaf(Fs[r][k], w, acc[r]);
    }

    float s=0.f, s2=0.f;
    #pragma unroll
    for (int r=0;r<CONV_ROWS;r++){
        float yv = acc[r];
        y[(size_t)(row0+r)*COc + o] = yv;
        s  += yv;
        s2 += yv*yv;
    }
    g_psum  [blk*COc + o] = s;
    g_psumsq[blk*COc + o] = s2;
}

// ---------------- BN stats (fixed-order, deterministic) ---------------------
__global__ __launch_bounds__(COc) void k_stats()
{
    int o = threadIdx.x;
    float s=0.f, s2=0.f;
    for (int i=0;i<CONV_BLOCKS;i++){
        s  += g_psum  [i*COc + o];
        s2 += g_psumsq[i*COc + o];
    }
    const float invM = 1.f / (float)ROWS_TOTAL;
    float mean = s * invM;
    float var  = s2 * invM - mean*mean;
    g_mean[o] = mean;
    g_rstd[o] = rsqrtf(var + 1e-5f);
}

// ---------------- BN apply + LeakyReLU --------------------------------------
__device__ __forceinline__ float bn_lrelu(float val, int o,
                                          const float* __restrict__ gamma,
                                          const float* __restrict__ beta){
    float z = (val - g_mean[o]) * g_rstd[o] * gamma[o] + beta[o];
    return z >= 0.f ? z : 0.01f*z;
}

__global__ __launch_bounds__(256) void k_apply(const float* __restrict__ gamma,
                                               const float* __restrict__ beta,
                                               float* __restrict__ y)
{
    int i = blockIdx.x*256 + threadIdx.x;
    const int total4 = Bc*Nc*COc/4;
    if (i >= total4) return;
    int o = (i*4) & (COc-1);
    float4 t = reinterpret_cast<float4*>(y)[i];
    t.x = bn_lrelu(t.x, o+0, gamma, beta);
    t.y = bn_lrelu(t.y, o+1, gamma, beta);
    t.z = bn_lrelu(t.z, o+2, gamma, beta);
    t.w = bn_lrelu(t.w, o+3, gamma, beta);
    reinterpret_cast<float4*>(y)[i] = t;
}

// ---------------- launch ----------------------------------------------------
extern "C" void kernel_launch(void* const* d_in, const int* in_sizes, int n_in,
                              void* d_out, int out_size)
{
    const float* x     = (const float*)d_in[0];
    const float* W     = (const float*)d_in[1];
    const float* gamma = (const float*)d_in[2];
    const float* beta  = (const float*)d_in[3];
    float* y = (float*)d_out;

    k_xx<<<ROWS_TOTAL/8, 256>>>(x);   // norms + zero all candidate counters

    dim3 dg(Nc/128, Nc/128);   // 32 x 32 tiles
    for (int b=0; b<Bc; b++){
        k_dist<<<dg, 256>>>(x, b);        // fused GEMM + candidate filter
        k_select<<<Nc/8, 256>>>(x, b);    // exact top-8 over ~600 candidates/row
    }

    k_conv<<<CONV_BLOCKS, 128>>>(W, y);
    k_stats<<<1, COc>>>();
    k_apply<<<(Bc*Nc*COc/4 + 255)/256, 256>>>(gamma, beta, y);
}

// round 6
// speedup vs baseline: 1.1374x; 1.1374x over previous
#include <cuda_runtime.h>

// Problem constants (shapes fixed by setup_inputs)
#define Bc   8
#define Nc   4096
#define Cc   64
#define COc  128
#define KNN  8
#define CAP  2048            /* candidate capacity per row (mean ~600, huge margin) */

#define ROWS_TOTAL   (Bc*Nc)           /* 32768 */
#define CONV_ROWS    16
#define CONV_BLOCKS  (ROWS_TOTAL/CONV_ROWS)  /* 2048 */

// ---------------- scratch (device globals: no runtime allocation) ----------
__device__ float g_xx[Bc*Nc];                       // per-point squared norms
__device__ int   g_cnt[Bc*Nc];                      // per-row candidate counts
__device__ uint2 g_cand[(size_t)Nc*CAP];            // 64MB candidate buffer (reused per batch)
__device__ float g_feat[(size_t)ROWS_TOTAL*Cc];     // 8MB  gathered-max features
__device__ float g_psum[CONV_BLOCKS*COc];           // BN partial sums (deterministic)
__device__ float g_psumsq[CONV_BLOCKS*COc];
__device__ float g_mean[COc];
__device__ float g_rstd[COc];

// ---------------- squared norms + counter zeroing ---------------------------
__global__ __launch_bounds__(256) void k_xx(const float* __restrict__ x)
{
    int gw   = (blockIdx.x*256 + threadIdx.x) >> 5;   // warp per row
    int lane = threadIdx.x & 31;
    if (gw >= ROWS_TOTAL) return;
    const float* xr = x + (size_t)gw*Cc;
    float a = xr[lane], b = xr[lane+32];
    float s = a*a + b*b;
    #pragma unroll
    for (int o=16;o;o>>=1) s += __shfl_xor_sync(0xffffffffu, s, o);
    if (lane == 0){ g_xx[gw] = s; g_cnt[gw] = 0; }
}

// ---------------- distance GEMM + fused per-tile top-k candidate filter -----
// D[n][m] = 2*<x_n,x_m> - xx_n - xx_m ; survivors (>= provably-safe per-tile
// threshold) are appended to per-row candidate lists. No 64MB dist matrix.
// __launch_bounds__(256,2): cap regs at 128 so 2 CTAs/SM stay resident (the
// R4 regression was a 152-reg / 1-CTA occupancy cliff). Epilogue-only spills.
__global__ __launch_bounds__(256, 2) void k_dist(const float* __restrict__ x, int b)
{
    __shared__ float As[32][128];   // k-major
    __shared__ float Bs[32][128];
    const float* xb = x + (size_t)b*Nc*Cc;
    const int n0  = blockIdx.y*128;
    const int m0  = blockIdx.x*128;
    const int tid = threadIdx.x;
    const int tx  = tid & 15;
    const int ty  = tid >> 4;
    const int lane = tid & 31;
    const int lgrp = lane & 15;     // position within the 16-lane row group
    const int lrow = tid & 127;
    const int lk0  = (tid >> 7) * 4;

    float acc[8][8];
    #pragma unroll
    for (int i=0;i<8;i++)
        #pragma unroll
        for (int j=0;j<8;j++) acc[i][j] = 0.f;

    #pragma unroll
    for (int kk=0; kk<2; kk++){
        #pragma unroll
        for (int i=0;i<4;i++){
            int k4 = lk0 + i*8;
            float4 a = *reinterpret_cast<const float4*>(&xb[(size_t)(n0+lrow)*Cc + kk*32 + k4]);
            As[k4+0][lrow]=a.x; As[k4+1][lrow]=a.y; As[k4+2][lrow]=a.z; As[k4+3][lrow]=a.w;
            float4 bb = *reinterpret_cast<const float4*>(&xb[(size_t)(m0+lrow)*Cc + kk*32 + k4]);
            Bs[k4+0][lrow]=bb.x; Bs[k4+1][lrow]=bb.y; Bs[k4+2][lrow]=bb.z; Bs[k4+3][lrow]=bb.w;
        }
        __syncthreads();
        #pragma unroll
        for (int k=0;k<32;k++){
            float4 a0 = *reinterpret_cast<const float4*>(&As[k][ty*4]);
            float4 a1 = *reinterpret_cast<const float4*>(&As[k][64+ty*4]);
            float4 b0 = *reinterpret_cast<const float4*>(&Bs[k][tx*4]);
            float4 b1 = *reinterpret_cast<const float4*>(&Bs[k][64+tx*4]);
            float av[8]={a0.x,a0.y,a0.z,a0.w,a1.x,a1.y,a1.z,a1.w};
            float bv[8]={b0.x,b0.y,b0.z,b0.w,b1.x,b1.y,b1.z,b1.w};
            #pragma unroll
            for (int i=0;i<8;i++)
                #pragma unroll
                for (int j=0;j<8;j++)
                    acc[i][j] = fmaf(av[i], bv[j], acc[i][j]);
        }
        __syncthreads();
    }

    // column-norm terms for this thread's 8 columns (may spill; epilogue-only)
    float mxx[8];
    #pragma unroll
    for (int cq=0;cq<2;cq++)
        #pragma unroll
        for (int c=0;c<4;c++)
            mxx[cq*4+c] = g_xx[b*Nc + m0 + cq*64 + tx*4 + c];

    // Epilogue: per row, build candidates. The 16 threads with the same ty
    // (lanes 0-15 or 16-31 of a warp) share the same 8 rows.
    #pragma unroll
    for (int rq=0;rq<2;rq++){
        #pragma unroll
        for (int r=0;r<4;r++){
            int row = n0 + rq*64 + ty*4 + r;
            float xn = g_xx[b*Nc + row];
            int ai = rq*4 + r;
            float d[8];
            #pragma unroll
            for (int j=0;j<8;j++) d[j] = fmaf(2.f, acc[ai][j], -(xn + mxx[j]));

            // threshold: min over 8 distinct 16-element block maxes
            // (t <= true 8th best of this tile row => no global top-8 lost)
            float m = d[0];
            #pragma unroll
            for (int j=1;j<8;j++) m = fmaxf(m, d[j]);
            float t = fmaxf(m, __shfl_xor_sync(0xffffffffu, m, 8));
            t = fminf(t, __shfl_xor_sync(0xffffffffu, t, 4));
            t = fminf(t, __shfl_xor_sync(0xffffffffu, t, 2));
            t = fminf(t, __shfl_xor_sync(0xffffffffu, t, 1));

            // flag survivors, prefix-scan counts over the 16-lane group
            int cnt = 0;
            bool f[8];
            #pragma unroll
            for (int j=0;j<8;j++){ f[j] = (d[j] >= t); cnt += f[j] ? 1 : 0; }
            int inc = cnt;
            #pragma unroll
            for (int o=1;o<16;o<<=1){
                int v = __shfl_up_sync(0xffffffffu, inc, o, 16);
                if (lgrp >= o) inc += v;
            }
            int total = __shfl_sync(0xffffffffu, inc, 15, 16);
            int base = 0;
            if (lgrp == 15) base = atomicAdd(&g_cnt[b*Nc + row], total);
            base = __shfl_sync(0xffffffffu, base, 15, 16);
            int off = base + inc - cnt;
            uint2* brow = &g_cand[(size_t)(row & (Nc-1))*CAP];
            #pragma unroll
            for (int j=0;j<8;j++){
                if (f[j]){
                    if (off < CAP){
                        int col = m0 + (j>>2)*64 + tx*4 + (j&3);
                        brow[off] = make_uint2(__float_as_uint(d[j]), (unsigned)col);
                    }
                    off++;
                }
            }
        }
    }
}

// ---------------- exact top-k(8) over candidates + gather + channel max -----
__device__ __forceinline__ bool knn_better(float v1,int i1,float v2,int i2){
    return (v1 > v2) || (v1 == v2 && i1 < i2);   // matches lax.top_k tie-break
}

__device__ __forceinline__ void knn_insert(float (&v)[8], int (&id)[8], float cv, int ci){
    if (!knn_better(cv,ci,v[7],id[7])) return;
    #pragma unroll
    for (int j=0;j<8;j++){
        if (knn_better(cv,ci,v[j],id[j])){
            float tv=v[j]; int ti=id[j];
            v[j]=cv; id[j]=ci;
            cv=tv; ci=ti;
        }
    }
}

__global__ __launch_bounds__(256) void k_select(const float* __restrict__ x, int b)
{
    int gw   = (blockIdx.x*256 + threadIdx.x) >> 5;   // warp per n-row
    int lane = threadIdx.x & 31;
    if (gw >= Nc) return;
    const int n = gw;
    int cnt = g_cnt[b*Nc + n];
    if (cnt > CAP) cnt = CAP;
    const uint2* brow = &g_cand[(size_t)n*CAP];

    float v[8]; int id[8];
    #pragma unroll
    for (int j=0;j<8;j++){ v[j] = __int_as_float(0xff800000u); id[j] = 0x7fffffff; }

    for (int ci = lane; ci < cnt; ci += 32){
        uint2 e = brow[ci];
        knn_insert(v, id, __uint_as_float(e.x), (int)e.y);
    }

    int knn_idx[8];
    #pragma unroll
    for (int r=0;r<KNN;r++){
        float bv = v[0]; int bi = id[0];
        #pragma unroll
        for (int o=16;o;o>>=1){
            float ov = __shfl_xor_sync(0xffffffffu, bv, o);
            int   oi = __shfl_xor_sync(0xffffffffu, bi, o);
            if (knn_better(ov,oi,bv,bi)){ bv=ov; bi=oi; }
        }
        knn_idx[r] = bi;                 // all lanes agree
        if (id[0] == bi){                // owning lane pops its head
            #pragma unroll
            for (int j=0;j<7;j++){ v[j]=v[j+1]; id[j]=id[j+1]; }
            v[7] = __int_as_float(0xff800000u); id[7] = 0x7fffffff;
        }
    }

    // gather neighbor features and take channel-wise max (exact, order-free)
    const float* xb = x + (size_t)b*Nc*Cc;
    #pragma unroll
    for (int cc=0; cc<2; cc++){
        int c = lane + cc*32;
        float m = xb[(size_t)knn_idx[0]*Cc + c];
        #pragma unroll
        for (int r=1;r<KNN;r++)
            m = fmaxf(m, xb[(size_t)knn_idx[r]*Cc + c]);
        g_feat[((size_t)b*Nc + n)*Cc + c] = m;
    }
}

// ---------------- 1x1 conv GEMM + deterministic BN partials -----------------
__global__ __launch_bounds__(128) void k_conv(const float* __restrict__ W,
                                              float* __restrict__ y)
{
    __shared__ float Ws[COc][Cc+1];   // +1 pad: conflict-free per-thread rows
    __shared__ float Fs[CONV_ROWS][Cc];
    const int t    = threadIdx.x;     // 128 threads == one output channel each
    const int blk  = blockIdx.x;
    const int row0 = blk*CONV_ROWS;

    for (int i=t; i<COc*Cc; i+=128) Ws[i>>6][i&63] = W[i];
    for (int i=t; i<CONV_ROWS*Cc; i+=128) Fs[i>>6][i&63] = g_feat[(size_t)row0*Cc + i];
    __syncthreads();

    const int o = t;
    float acc[CONV_ROWS];
    #pragma unroll
    for (int r=0;r<CONV_ROWS;r++) acc[r]=0.f;

    #pragma unroll 8
    for (int k=0;k<Cc;k++){
        float w = Ws[o][k];
        #pragma unroll
        for (int r=0;r<CONV_ROWS;r++)
            acc[r] = fmaf(Fs[r][k], w, acc[r]);
    }

    float s=0.f, s2=0.f;
    #pragma unroll
    for (int r=0;r<CONV_ROWS;r++){
        float yv = acc[r];
        y[(size_t)(row0+r)*COc + o] = yv;
        s  += yv;
        s2 += yv*yv;
    }
    g_psum  [blk*COc + o] = s;
    g_psumsq[blk*COc + o] = s2;
}

// ---------------- BN stats (fixed-order, deterministic) ---------------------
__global__ __launch_bounds__(COc) void k_stats()
{
    int o = threadIdx.x;
    float s=0.f, s2=0.f;
    for (int i=0;i<CONV_BLOCKS;i++){
        s  += g_psum  [i*COc + o];
        s2 += g_psumsq[i*COc + o];
    }
    const float invM = 1.f / (float)ROWS_TOTAL;
    float mean = s * invM;
    float var  = s2 * invM - mean*mean;
    g_mean[o] = mean;
    g_rstd[o] = rsqrtf(var + 1e-5f);
}

// ---------------- BN apply + LeakyReLU --------------------------------------
__device__ __forceinline__ float bn_lrelu(float val, int o,
                                          const float* __restrict__ gamma,
                                          const float* __restrict__ beta){
    float z = (val - g_mean[o]) * g_rstd[o] * gamma[o] + beta[o];
    return z >= 0.f ? z : 0.01f*z;
}

__global__ __launch_bounds__(256) void k_apply(const float* __restrict__ gamma,
                                               const float* __restrict__ beta,
                                               float* __restrict__ y)
{
    int i = blockIdx.x*256 + threadIdx.x;
    const int total4 = Bc*Nc*COc/4;
    if (i >= total4) return;
    int o = (i*4) & (COc-1);
    float4 t = reinterpret_cast<float4*>(y)[i];
    t.x = bn_lrelu(t.x, o+0, gamma, beta);
    t.y = bn_lrelu(t.y, o+1, gamma, beta);
    t.z = bn_lrelu(t.z, o+2, gamma, beta);
    t.w = bn_lrelu(t.w, o+3, gamma, beta);
    reinterpret_cast<float4*>(y)[i] = t;
}

// ---------------- launch ----------------------------------------------------
extern "C" void kernel_launch(void* const* d_in, const int* in_sizes, int n_in,
                              void* d_out, int out_size)
{
    const float* x     = (const float*)d_in[0];
    const float* W     = (const float*)d_in[1];
    const float* gamma = (const float*)d_in[2];
    const float* beta  = (const float*)d_in[3];
    float* y = (float*)d_out;

    k_xx<<<ROWS_TOTAL/8, 256>>>(x);   // norms + zero all candidate counters

    dim3 dg(Nc/128, Nc/128);   // 32 x 32 tiles
    for (int b=0; b<Bc; b++){
        k_dist<<<dg, 256>>>(x, b);        // fused GEMM + candidate filter
        k_select<<<Nc/8, 256>>>(x, b);    // exact top-8 over ~600 candidates/row
    }

    k_conv<<<CONV_BLOCKS, 128>>>(W, y);
    k_stats<<<1, COc>>>();
    k_apply<<<(Bc*Nc*COc/4 + 255)/256, 256>>>(gamma, beta, y);
}